// round 9
// baseline (speedup 1.0000x reference)
#include <cuda_runtime.h>
#include <cuda_bf16.h>
#include <cstdint>

// ---------------------------------------------------------------------------
// NonLocal2D collapsed to per-batch affine map:
//   S = x x^T - s s^T/N,  W = A S B,  beff = A S v + out_b,
//   A = out_w g_w,  B = phi^T theta',  v = phi^T theta'_b   (batch-independent)
//   out = x + W x + beff.
// Large GEMMs (Gram, apply) on mma.sync bf16 with hi/lo split (3 passes).
// R8/R9: fp32->bf16 conversion fused into gram/apply mainloops (register-
//     staged), rowsum fused into gram, chain collapsed to A S B (2 serial
//     GEMMs), MLP-unrolled reduce producing S directly.
// ---------------------------------------------------------------------------

#define BATCH 4
#define C     256
#define CI    128
#define NSP   4096
#define KS    12
#define INV_N (1.0f / 4096.0f)
#define GR_PAD 40              // bf16 row stride 80B: ldmatrix conflict-free
#define AP_BPAD 136            // bf16 row stride 272B: trans-ldmatrix conflict-free
#define NB    288              // padded N for Bext/T (256 W cols + beff col + pad)

// ------------------------- device scratch ----------------------------------
__device__ float d_Gp[KS][BATCH][3][128][128];
__device__ float d_sp[KS][BATCH][C];
__device__ float d_S [BATCH][C][C];
__device__ float d_thpw[CI * C];
__device__ float d_thpb[CI];
__device__ float d_A   [C * C];
__device__ float d_Bext[C][NB];
__device__ float d_T [BATCH][C][NB];
__device__ __nv_bfloat16 d_Whi[BATCH][C][C];
__device__ __nv_bfloat16 d_Wlo[BATCH][C][C];
__device__ float d_beff[BATCH][C];

// ------------------------- helpers -----------------------------------------
__device__ __forceinline__ uint32_t smem_u32(const void* p) {
    uint32_t a;
    asm("{ .reg .u64 t; cvta.to.shared.u64 t, %1; cvt.u32.u64 %0, t; }"
        : "=r"(a) : "l"(p));
    return a;
}
__device__ __forceinline__ void ldsm_x4(uint32_t* r, uint32_t addr) {
    asm volatile("ldmatrix.sync.aligned.m8n8.x4.shared.b16 {%0,%1,%2,%3}, [%4];"
                 : "=r"(r[0]), "=r"(r[1]), "=r"(r[2]), "=r"(r[3]) : "r"(addr));
}
__device__ __forceinline__ void ldsm_x4_t(uint32_t* r, uint32_t addr) {
    asm volatile("ldmatrix.sync.aligned.m8n8.x4.trans.shared.b16 {%0,%1,%2,%3}, [%4];"
                 : "=r"(r[0]), "=r"(r[1]), "=r"(r[2]), "=r"(r[3]) : "r"(addr));
}
__device__ __forceinline__ void mma16816(float* d, const uint32_t* a, const uint32_t* b) {
    asm volatile(
        "mma.sync.aligned.m16n8k16.row.col.f32.bf16.bf16.f32 "
        "{%0,%1,%2,%3}, {%4,%5,%6,%7}, {%8,%9}, {%0,%1,%2,%3};"
        : "+f"(d[0]), "+f"(d[1]), "+f"(d[2]), "+f"(d[3])
        : "r"(a[0]), "r"(a[1]), "r"(a[2]), "r"(a[3]), "r"(b[0]), "r"(b[1]));
}
__device__ __forceinline__ void split16(const float* f, __nv_bfloat16* h, __nv_bfloat16* l) {
#pragma unroll
    for (int j = 0; j < 16; j++) {
        h[j] = __float2bfloat16(f[j]);
        l[j] = __float2bfloat16(f[j] - __bfloat162float(h[j]));
    }
}

// ---------------------------------------------------------------------------
// theta' prep
__global__ void k_theta_prep(const float* __restrict__ tw, const float* __restrict__ tb) {
    const int c = blockIdx.x, o = threadIdx.x;     // 256 blocks x 128 threads
    __shared__ float sm[128];
    float v = tw[o * C + c];
    sm[o] = v; __syncthreads();
    for (int s = 64; s > 0; s >>= 1) { if (o < s) sm[o] += sm[o + s]; __syncthreads(); }
    d_thpw[o * C + c] = v - sm[0] * (1.0f / CI);
    if (c == 0) {
        float vb = tb[o];
        __syncthreads();
        sm[o] = vb; __syncthreads();
        for (int s = 64; s > 0; s >>= 1) { if (o < s) sm[o] += sm[o + s]; __syncthreads(); }
        d_thpb[o] = vb - sm[0] * (1.0f / CI);
    }
}

// ---------------------------------------------------------------------------
// A = out_w g_w (z=0), Bext = [phi^T theta' | phi^T theta'_b | 0] (z=1). K=128.
__global__ void __launch_bounds__(256) k_ab(const float* __restrict__ out_w,
                                            const float* __restrict__ g_w,
                                            const float* __restrict__ phi_w) {
    const int z = blockIdx.z;
    const int m0 = blockIdx.y * 32, n0 = blockIdx.x * 32;
    if (z == 0 && n0 >= C) return;
    __shared__ float As[32][33];
    __shared__ float Bs[32][33];
    const int tx = threadIdx.x & 15, ty = threadIdx.x >> 4;
    const int c0 = threadIdx.x & 31, r0 = threadIdx.x >> 5;
    float a00 = 0.f, a01 = 0.f, a10 = 0.f, a11 = 0.f;
    for (int k0 = 0; k0 < CI; k0 += 32) {
#pragma unroll
        for (int p = 0; p < 4; p++) {
            int r = r0 + p * 8;
            As[c0][r] = z == 0 ? out_w[(m0 + r) * CI + k0 + c0]
                               : phi_w[(k0 + c0) * C + m0 + r];
            int n = n0 + c0;
            float bv;
            if (z == 0)          bv = g_w[(k0 + r) * C + n];
            else if (n < C)      bv = d_thpw[(k0 + r) * C + n];
            else if (n == C)     bv = d_thpb[k0 + r];
            else                 bv = 0.f;
            Bs[r][c0] = bv;
        }
        __syncthreads();
#pragma unroll
        for (int k = 0; k < 32; k++) {
            float a0 = As[k][ty * 2], a1 = As[k][ty * 2 + 1];
            float b0 = Bs[k][tx * 2], b1 = Bs[k][tx * 2 + 1];
            a00 += a0 * b0; a01 += a0 * b1; a10 += a1 * b0; a11 += a1 * b1;
        }
        __syncthreads();
    }
    const int m = m0 + ty * 2, n = n0 + tx * 2;
    if (z == 0) {
        d_A[m * C + n] = a00;       d_A[m * C + n + 1] = a01;
        d_A[(m + 1) * C + n] = a10; d_A[(m + 1) * C + n + 1] = a11;
    } else {
        d_Bext[m][n] = a00;       d_Bext[m][n + 1] = a01;
        d_Bext[m + 1][n] = a10;   d_Bext[m + 1][n + 1] = a11;
    }
}

// ---------------------------------------------------------------------------
// Gram: CTA = one 128x128 tile (3 unique symmetric tiles), split-K over KS=12
// (144 CTAs = one wave). Reads fp32 x, converts to bf16 hi/lo in-kernel,
// register double-buffered. Diagonal CTAs also accumulate row sums -> d_sp.
__global__ void __launch_bounds__(256) k_gram_mma(const float* __restrict__ x) {
    __shared__ __nv_bfloat16 sA[2][128][GR_PAD];
    __shared__ __nv_bfloat16 sB[2][128][GR_PAD];
    __shared__ float rs[128][2];
    const int tid = threadIdx.x, wid = tid >> 5, lane = tid & 31;
    const int t = blockIdx.x, ks = blockIdx.y, b = blockIdx.z;
    const int tr = (t == 2) ? 128 : 0, tc = (t == 0) ? 0 : 128;
    const bool diag = (t != 1);
    const int wm = (wid & 1) * 64, wn = (wid >> 1) * 32;
    float acc[4][4][4] = {};
    const int base = ks * 10 + (ks < 8 ? ks : 8);
    const int cnt  = (ks < 8) ? 11 : 10;

    const int r = tid >> 1, h = tid & 1;          // staging: row r, cols h*16..
    const float* xa = x + ((size_t)b * C + tr + r) * NSP;
    const float* xb = x + ((size_t)b * C + tc + r) * NSP;
    float ra[16], rb[16];
    float rsum = 0.f;

    // prologue load
#pragma unroll
    for (int j = 0; j < 4; j++)
        *(float4*)(ra + 4 * j) = *(const float4*)(xa + base * 32 + h * 16 + 4 * j);
    if (!diag)
#pragma unroll
        for (int j = 0; j < 4; j++)
            *(float4*)(rb + 4 * j) = *(const float4*)(xb + base * 32 + h * 16 + 4 * j);

    const uint32_t sAu = smem_u32(&sA[0][0][0]);
    const uint32_t sBu = diag ? sAu : smem_u32(&sB[0][0][0]);
    const uint32_t loP = 128 * GR_PAD * 2;        // hi->lo plane byte offset

    for (int c = 0; c < cnt; c++) {
        __syncthreads();                           // prior mma done with smem
        {   // convert + STS + rowsum
            __nv_bfloat16 hb[16], lb[16];
            split16(ra, hb, lb);
            *(uint4*)&sA[0][r][h * 16]     = *(uint4*)&hb[0];
            *(uint4*)&sA[0][r][h * 16 + 8] = *(uint4*)&hb[8];
            *(uint4*)&sA[1][r][h * 16]     = *(uint4*)&lb[0];
            *(uint4*)&sA[1][r][h * 16 + 8] = *(uint4*)&lb[8];
            if (diag) {
#pragma unroll
                for (int j = 0; j < 16; j++) rsum += ra[j];
            } else {
                split16(rb, hb, lb);
                *(uint4*)&sB[0][r][h * 16]     = *(uint4*)&hb[0];
                *(uint4*)&sB[0][r][h * 16 + 8] = *(uint4*)&hb[8];
                *(uint4*)&sB[1][r][h * 16]     = *(uint4*)&lb[0];
                *(uint4*)&sB[1][r][h * 16 + 8] = *(uint4*)&lb[8];
            }
        }
        __syncthreads();
        if (c + 1 < cnt) {                         // prefetch next chunk
            const int kb = (base + c + 1) * 32;
#pragma unroll
            for (int j = 0; j < 4; j++)
                *(float4*)(ra + 4 * j) = *(const float4*)(xa + kb + h * 16 + 4 * j);
            if (!diag)
#pragma unroll
                for (int j = 0; j < 4; j++)
                    *(float4*)(rb + 4 * j) = *(const float4*)(xb + kb + h * 16 + 4 * j);
        }
#pragma unroll
        for (int kk = 0; kk < 32; kk += 16) {
            uint32_t ah[4][4], al[4][4], bh[2][4], bl[2][4];
            const int arow = lane & 15, acol = kk + (lane >> 4) * 8;
#pragma unroll
            for (int i = 0; i < 4; i++) {
                uint32_t ad = sAu + (uint32_t)((wm + i * 16 + arow) * GR_PAD + acol) * 2;
                ldsm_x4(ah[i], ad);
                ldsm_x4(al[i], ad + loP);
            }
            const int bn = (lane & 7) + (lane >> 4) * 8;
            const int bcol = kk + ((lane >> 3) & 1) * 8;
#pragma unroll
            for (int j = 0; j < 2; j++) {
                uint32_t bd = sBu + (uint32_t)((wn + j * 16 + bn) * GR_PAD + bcol) * 2;
                ldsm_x4(bh[j], bd);
                ldsm_x4(bl[j], bd + loP);
            }
#pragma unroll
            for (int i = 0; i < 4; i++)
#pragma unroll
                for (int jj = 0; jj < 4; jj++) {
                    const uint32_t* ph = &bh[jj >> 1][(jj & 1) * 2];
                    const uint32_t* pl = &bl[jj >> 1][(jj & 1) * 2];
                    mma16816(acc[i][jj], ah[i], ph);
                    mma16816(acc[i][jj], ah[i], pl);
                    mma16816(acc[i][jj], al[i], ph);
                }
        }
    }
    // row-sum epilogue (diag CTAs cover all 256 rows exactly once)
    if (diag) {
        __syncthreads();
        rs[r][h] = rsum;
        __syncthreads();
        if (tid < 128) d_sp[ks][b][tr + tid] = rs[tid][0] + rs[tid][1];
    }
#pragma unroll
    for (int i = 0; i < 4; i++)
#pragma unroll
        for (int jj = 0; jj < 4; jj++) {
            int rl = wm + i * 16 + (lane >> 2);
            int cl = wn + jj * 8 + (lane & 3) * 2;
            *(float2*)&d_Gp[ks][b][t][rl][cl]     = make_float2(acc[i][jj][0], acc[i][jj][1]);
            *(float2*)&d_Gp[ks][b][t][rl + 8][cl] = make_float2(acc[i][jj][2], acc[i][jj][3]);
        }
}

// ---------------------------------------------------------------------------
// reduce split-K partials + rowsum partials -> S = G - s s^T/N (with mirror)
__global__ void __launch_bounds__(256) k_reduce_s() {
    const int t = blockIdx.x, b = blockIdx.y;
    const int tid = threadIdx.x;
    const int Rb = (t == 2) ? 128 : 0, Cb = (t == 0) ? 0 : 128;
    __shared__ float sR[128], sC[128];
    if (tid < 128) {
        float a = 0.f;
#pragma unroll
        for (int p = 0; p < KS; p++) a += d_sp[p][b][Rb + tid];
        sR[tid] = a;
    } else {
        float a = 0.f;
#pragma unroll
        for (int p = 0; p < KS; p++) a += d_sp[p][b][Cb + tid - 128];
        sC[tid - 128] = a;
    }
    __syncthreads();
#pragma unroll
    for (int q = 0; q < 16; q++) {
        int idx = tid + q * 256;                   // 4096 float4 positions
        int row = idx >> 5, c4 = (idx & 31) * 4;
        float4 a = make_float4(0.f, 0.f, 0.f, 0.f);
#pragma unroll
        for (int p = 0; p < KS; p++) {
            float4 v = *(const float4*)&d_Gp[p][b][t][row][c4];
            a.x += v.x; a.y += v.y; a.z += v.z; a.w += v.w;
        }
        float sr = sR[row] * INV_N;
        a.x -= sr * sC[c4];     a.y -= sr * sC[c4 + 1];
        a.z -= sr * sC[c4 + 2]; a.w -= sr * sC[c4 + 3];
        *(float4*)&d_S[b][Rb + row][Cb + c4] = a;
        if (t == 1) {
            d_S[b][Cb + c4][Rb + row]     = a.x;
            d_S[b][Cb + c4 + 1][Rb + row] = a.y;
            d_S[b][Cb + c4 + 2][Rb + row] = a.z;
            d_S[b][Cb + c4 + 3][Rb + row] = a.w;
        }
    }
}

// ---------------------------------------------------------------------------
// T = S * Bext  (256 x 288, K=256) per batch
__global__ void __launch_bounds__(256) k_T() {
    const int b = blockIdx.z;
    const int m0 = blockIdx.y * 32, n0 = blockIdx.x * 32;
    __shared__ float As[32][33];
    __shared__ float Bs[32][33];
    const int tx = threadIdx.x & 15, ty = threadIdx.x >> 4;
    const int c0 = threadIdx.x & 31, r0 = threadIdx.x >> 5;
    float a00 = 0.f, a01 = 0.f, a10 = 0.f, a11 = 0.f;
    for (int k0 = 0; k0 < C; k0 += 32) {
#pragma unroll
        for (int p = 0; p < 4; p++) {
            int r = r0 + p * 8;
            As[c0][r] = d_S[b][m0 + r][k0 + c0];
            Bs[r][c0] = d_Bext[k0 + r][n0 + c0];
        }
        __syncthreads();
#pragma unroll
        for (int k = 0; k < 32; k++) {
            float a0 = As[k][ty * 2], a1 = As[k][ty * 2 + 1];
            float b0 = Bs[k][tx * 2], b1 = Bs[k][tx * 2 + 1];
            a00 += a0 * b0; a01 += a0 * b1; a10 += a1 * b0; a11 += a1 * b1;
        }
        __syncthreads();
    }
    const int m = m0 + ty * 2, n = n0 + tx * 2;
    d_T[b][m][n] = a00;     d_T[b][m][n + 1] = a01;
    d_T[b][m + 1][n] = a10; d_T[b][m + 1][n + 1] = a11;
}

// ---------------------------------------------------------------------------
// W = A * T (store hi/lo), col 256 -> beff = A S v + out_b
__global__ void __launch_bounds__(256) k_W(const float* __restrict__ out_b) {
    const int b = blockIdx.z;
    const int m0 = blockIdx.y * 32, n0 = blockIdx.x * 32;
    __shared__ float As[32][33];
    __shared__ float Bs[32][33];
    const int tx = threadIdx.x & 15, ty = threadIdx.x >> 4;
    const int c0 = threadIdx.x & 31, r0 = threadIdx.x >> 5;
    float a00 = 0.f, a01 = 0.f, a10 = 0.f, a11 = 0.f;
    for (int k0 = 0; k0 < C; k0 += 32) {
#pragma unroll
        for (int p = 0; p < 4; p++) {
            int r = r0 + p * 8;
            As[c0][r] = d_A[(m0 + r) * C + k0 + c0];
            Bs[r][c0] = d_T[b][k0 + r][n0 + c0];
        }
        __syncthreads();
#pragma unroll
        for (int k = 0; k < 32; k++) {
            float a0 = As[k][ty * 2], a1 = As[k][ty * 2 + 1];
            float b0 = Bs[k][tx * 2], b1 = Bs[k][tx * 2 + 1];
            a00 += a0 * b0; a01 += a0 * b1; a10 += a1 * b0; a11 += a1 * b1;
        }
        __syncthreads();
    }
    const int m = m0 + ty * 2, n = n0 + tx * 2;
    float vals[2][2] = {{a00, a01}, {a10, a11}};
#pragma unroll
    for (int i = 0; i < 2; i++)
#pragma unroll
        for (int j = 0; j < 2; j++) {
            int mm = m + i, nn = n + j;
            float v = vals[i][j];
            if (nn < C) {
                __nv_bfloat16 hh = __float2bfloat16(v);
                d_Whi[b][mm][nn] = hh;
                d_Wlo[b][mm][nn] = __float2bfloat16(v - __bfloat162float(hh));
            } else if (nn == C) {
                d_beff[b][mm] = v + out_b[mm];
            }
        }
}

// ---------------------------------------------------------------------------
// apply: out = x + W x + beff. CTA 128(ch) x 128(sp), K=256.
// W tiles from d_Whi/d_Wlo; x tiles fp32->bf16 converted in-kernel.
__global__ void __launch_bounds__(256) k_apply_mma(const float* __restrict__ x,
                                                   float* __restrict__ outp) {
    __shared__ __nv_bfloat16 sW[2][128][GR_PAD];
    __shared__ __nv_bfloat16 sX[2][32][AP_BPAD];
    const int tid = threadIdx.x, wid = tid >> 5, lane = tid & 31;
    const int m0 = blockIdx.y * 128, n0 = blockIdx.x * 128, b = blockIdx.z;
    const int wm = (wid & 1) * 64, wn = (wid >> 1) * 32;
    float acc[4][4][4] = {};

    const int rw = tid >> 1, hw = tid & 1;         // W staging
    const int xr = tid >> 3, xh = tid & 7;         // x staging
    uint4 wh[2], wl[2];
    float xf[16];

    // prologue load (chunk 0)
    wh[0] = *(const uint4*)&d_Whi[b][m0 + rw][hw * 16];
    wh[1] = *(const uint4*)&d_Whi[b][m0 + rw][hw * 16 + 8];
    wl[0] = *(const uint4*)&d_Wlo[b][m0 + rw][hw * 16];
    wl[1] = *(const uint4*)&d_Wlo[b][m0 + rw][hw * 16 + 8];
#pragma unroll
    for (int j = 0; j < 4; j++)
        *(float4*)(xf + 4 * j) =
            *(const float4*)(x + ((size_t)b * C + xr) * NSP + n0 + xh * 16 + 4 * j);

    const uint32_t sWu = smem_u32(&sW[0][0][0]);
    const uint32_t sXu = smem_u32(&sX[0][0][0]);
    const uint32_t loW = 128 * GR_PAD * 2;
    const uint32_t loX = 32 * AP_BPAD * 2;

    for (int kc = 0; kc < 8; kc++) {
        __syncthreads();
        {   // stage W + convert x
            *(uint4*)&sW[0][rw][hw * 16]     = wh[0];
            *(uint4*)&sW[0][rw][hw * 16 + 8] = wh[1];
            *(uint4*)&sW[1][rw][hw * 16]     = wl[0];
            *(uint4*)&sW[1][rw][hw * 16 + 8] = wl[1];
            __nv_bfloat16 hb[16], lb[16];
            split16(xf, hb, lb);
            *(uint4*)&sX[0][xr][xh * 16]     = *(uint4*)&hb[0];
            *(uint4*)&sX[0][xr][xh * 16 + 8] = *(uint4*)&hb[8];
            *(uint4*)&sX[1][xr][xh * 16]     = *(uint4*)&lb[0];
            *(uint4*)&sX[1][xr][xh * 16 + 8] = *(uint4*)&lb[8];
        }
        __syncthreads();
        if (kc + 1 < 8) {                          // prefetch next chunk
            const int kb = (kc + 1) * 32;
            wh[0] = *(const uint4*)&d_Whi[b][m0 + rw][kb + hw * 16];
            wh[1] = *(const uint4*)&d_Whi[b][m0 + rw][kb + hw * 16 + 8];
            wl[0] = *(const uint4*)&d_Wlo[b][m0 + rw][kb + hw * 16];
            wl[1] = *(const uint4*)&d_Wlo[b][m0 + rw][kb + hw * 16 + 8];
#pragma unroll
            for (int j = 0; j < 4; j++)
                *(float4*)(xf + 4 * j) =
                    *(const float4*)(x + ((size_t)b * C + kb + xr) * NSP + n0 + xh * 16 + 4 * j);
        }
#pragma unroll
        for (int kk = 0; kk < 32; kk += 16) {
            uint32_t ah[4][4], al[4][4], bh[2][4], bl[2][4];
            const int arow = lane & 15, acol = kk + (lane >> 4) * 8;
#pragma unroll
            for (int i = 0; i < 4; i++) {
                uint32_t ad = sWu + (uint32_t)((wm + i * 16 + arow) * GR_PAD + acol) * 2;
                ldsm_x4(ah[i], ad);
                ldsm_x4(al[i], ad + loW);
            }
            const int krow = kk + (lane & 7) + ((lane >> 3) & 1) * 8;
            const int ncol = ((lane >> 4) & 1) * 8;
#pragma unroll
            for (int j = 0; j < 2; j++) {
                uint32_t bd = sXu + (uint32_t)(krow * AP_BPAD + wn + j * 16 + ncol) * 2;
                ldsm_x4_t(bh[j], bd);
                ldsm_x4_t(bl[j], bd + loX);
            }
#pragma unroll
            for (int i = 0; i < 4; i++)
#pragma unroll
                for (int jj = 0; jj < 4; jj++) {
                    const uint32_t* ph = &bh[jj >> 1][(jj & 1) * 2];
                    const uint32_t* pl = &bl[jj >> 1][(jj & 1) * 2];
                    mma16816(acc[i][jj], ah[i], ph);
                    mma16816(acc[i][jj], ah[i], pl);
                    mma16816(acc[i][jj], al[i], ph);
                }
        }
    }
    // epilogue: + x + beff
#pragma unroll
    for (int i = 0; i < 4; i++) {
        int r0g = m0 + wm + i * 16 + (lane >> 2);
        float be0 = d_beff[b][r0g], be1 = d_beff[b][r0g + 8];
        const float* x0 = x + ((size_t)b * C + r0g) * NSP + n0;
        float* o0 = outp + ((size_t)b * C + r0g) * NSP + n0;
#pragma unroll
        for (int jj = 0; jj < 4; jj++) {
            int cl = wn + jj * 8 + (lane & 3) * 2;
            float2 xa = *(const float2*)(x0 + cl);
            float2 xb = *(const float2*)(x0 + 8 * NSP + cl);
            float2 oa = make_float2(acc[i][jj][0] + xa.x + be0, acc[i][jj][1] + xa.y + be0);
            float2 ob = make_float2(acc[i][jj][2] + xb.x + be1, acc[i][jj][3] + xb.y + be1);
            *(float2*)(o0 + cl) = oa;
            *(float2*)(o0 + 8 * NSP + cl) = ob;
        }
    }
}

// ---------------------------------------------------------------------------
extern "C" void kernel_launch(void* const* d_in, const int* in_sizes, int n_in,
                              void* d_out, int out_size) {
    const float* x       = (const float*)d_in[0];
    const float* g_w     = (const float*)d_in[1];
    const float* theta_w = (const float*)d_in[3];
    const float* theta_b = (const float*)d_in[4];
    const float* phi_w   = (const float*)d_in[5];
    const float* out_w   = (const float*)d_in[7];
    const float* out_b   = (const float*)d_in[8];
    float* out = (float*)d_out;

    k_theta_prep<<<C, 128>>>(theta_w, theta_b);
    k_ab<<<dim3(NB / 32, C / 32, 2), 256>>>(out_w, g_w, phi_w);
    k_gram_mma<<<dim3(3, KS, BATCH), 256>>>(x);
    k_reduce_s<<<dim3(3, BATCH), 256>>>();
    k_T<<<dim3(NB / 32, C / 32, BATCH), 256>>>();
    k_W<<<dim3(NB / 32, C / 32, BATCH), 256>>>(out_b);
    k_apply_mma<<<dim3(NSP / 128, C / 128, BATCH), 256>>>(x, out);
}

// round 11
// speedup vs baseline: 1.1946x; 1.1946x over previous
#include <cuda_runtime.h>
#include <cuda_bf16.h>
#include <cstdint>

// ---------------------------------------------------------------------------
// NonLocal2D collapsed to per-batch affine map:
//   S = x x^T - s s^T/N,  W = A S B,  beff = A S v + out_b,
//   A = out_w g_w,  B = phi^T theta',  v = phi^T theta'_b   (batch-independent)
//   out = x + W x + beff.
// Large GEMMs (Gram, apply) on mma.sync bf16 with hi/lo split (3 passes).
// R10: k_reduce_s re-parallelized (192 CTAs, 1 f4/thread, 12-plane unroll) —
//      R9's 12-CTA version was the 36.7us bottleneck.
// ---------------------------------------------------------------------------

#define BATCH 4
#define C     256
#define CI    128
#define NSP   4096
#define KS    12
#define INV_N (1.0f / 4096.0f)
#define GR_PAD 40              // bf16 row stride 80B: ldmatrix conflict-free
#define AP_BPAD 136            // bf16 row stride 272B: trans-ldmatrix conflict-free
#define NB    288              // padded N for Bext/T (256 W cols + beff col + pad)

// ------------------------- device scratch ----------------------------------
__device__ float d_Gp[KS][BATCH][3][128][128];
__device__ float d_sp[KS][BATCH][C];
__device__ float d_S [BATCH][C][C];
__device__ float d_thpw[CI * C];
__device__ float d_thpb[CI];
__device__ float d_A   [C * C];
__device__ float d_Bext[C][NB];
__device__ float d_T [BATCH][C][NB];
__device__ __nv_bfloat16 d_Whi[BATCH][C][C];
__device__ __nv_bfloat16 d_Wlo[BATCH][C][C];
__device__ float d_beff[BATCH][C];

// ------------------------- helpers -----------------------------------------
__device__ __forceinline__ uint32_t smem_u32(const void* p) {
    uint32_t a;
    asm("{ .reg .u64 t; cvta.to.shared.u64 t, %1; cvt.u32.u64 %0, t; }"
        : "=r"(a) : "l"(p));
    return a;
}
__device__ __forceinline__ void ldsm_x4(uint32_t* r, uint32_t addr) {
    asm volatile("ldmatrix.sync.aligned.m8n8.x4.shared.b16 {%0,%1,%2,%3}, [%4];"
                 : "=r"(r[0]), "=r"(r[1]), "=r"(r[2]), "=r"(r[3]) : "r"(addr));
}
__device__ __forceinline__ void ldsm_x4_t(uint32_t* r, uint32_t addr) {
    asm volatile("ldmatrix.sync.aligned.m8n8.x4.trans.shared.b16 {%0,%1,%2,%3}, [%4];"
                 : "=r"(r[0]), "=r"(r[1]), "=r"(r[2]), "=r"(r[3]) : "r"(addr));
}
__device__ __forceinline__ void mma16816(float* d, const uint32_t* a, const uint32_t* b) {
    asm volatile(
        "mma.sync.aligned.m16n8k16.row.col.f32.bf16.bf16.f32 "
        "{%0,%1,%2,%3}, {%4,%5,%6,%7}, {%8,%9}, {%0,%1,%2,%3};"
        : "+f"(d[0]), "+f"(d[1]), "+f"(d[2]), "+f"(d[3])
        : "r"(a[0]), "r"(a[1]), "r"(a[2]), "r"(a[3]), "r"(b[0]), "r"(b[1]));
}
__device__ __forceinline__ void split16(const float* f, __nv_bfloat16* h, __nv_bfloat16* l) {
#pragma unroll
    for (int j = 0; j < 16; j++) {
        h[j] = __float2bfloat16(f[j]);
        l[j] = __float2bfloat16(f[j] - __bfloat162float(h[j]));
    }
}

// ---------------------------------------------------------------------------
// theta' prep
__global__ void k_theta_prep(const float* __restrict__ tw, const float* __restrict__ tb) {
    const int c = blockIdx.x, o = threadIdx.x;     // 256 blocks x 128 threads
    __shared__ float sm[128];
    float v = tw[o * C + c];
    sm[o] = v; __syncthreads();
    for (int s = 64; s > 0; s >>= 1) { if (o < s) sm[o] += sm[o + s]; __syncthreads(); }
    d_thpw[o * C + c] = v - sm[0] * (1.0f / CI);
    if (c == 0) {
        float vb = tb[o];
        __syncthreads();
        sm[o] = vb; __syncthreads();
        for (int s = 64; s > 0; s >>= 1) { if (o < s) sm[o] += sm[o + s]; __syncthreads(); }
        d_thpb[o] = vb - sm[0] * (1.0f / CI);
    }
}

// ---------------------------------------------------------------------------
// A = out_w g_w (z=0), Bext = [phi^T theta' | phi^T theta'_b | 0] (z=1). K=128.
__global__ void __launch_bounds__(256) k_ab(const float* __restrict__ out_w,
                                            const float* __restrict__ g_w,
                                            const float* __restrict__ phi_w) {
    const int z = blockIdx.z;
    const int m0 = blockIdx.y * 32, n0 = blockIdx.x * 32;
    if (z == 0 && n0 >= C) return;
    __shared__ float As[32][33];
    __shared__ float Bs[32][33];
    const int tx = threadIdx.x & 15, ty = threadIdx.x >> 4;
    const int c0 = threadIdx.x & 31, r0 = threadIdx.x >> 5;
    float a00 = 0.f, a01 = 0.f, a10 = 0.f, a11 = 0.f;
    for (int k0 = 0; k0 < CI; k0 += 32) {
#pragma unroll
        for (int p = 0; p < 4; p++) {
            int r = r0 + p * 8;
            As[c0][r] = z == 0 ? out_w[(m0 + r) * CI + k0 + c0]
                               : phi_w[(k0 + c0) * C + m0 + r];
            int n = n0 + c0;
            float bv;
            if (z == 0)          bv = g_w[(k0 + r) * C + n];
            else if (n < C)      bv = d_thpw[(k0 + r) * C + n];
            else if (n == C)     bv = d_thpb[k0 + r];
            else                 bv = 0.f;
            Bs[r][c0] = bv;
        }
        __syncthreads();
#pragma unroll
        for (int k = 0; k < 32; k++) {
            float a0 = As[k][ty * 2], a1 = As[k][ty * 2 + 1];
            float b0 = Bs[k][tx * 2], b1 = Bs[k][tx * 2 + 1];
            a00 += a0 * b0; a01 += a0 * b1; a10 += a1 * b0; a11 += a1 * b1;
        }
        __syncthreads();
    }
    const int m = m0 + ty * 2, n = n0 + tx * 2;
    if (z == 0) {
        d_A[m * C + n] = a00;       d_A[m * C + n + 1] = a01;
        d_A[(m + 1) * C + n] = a10; d_A[(m + 1) * C + n + 1] = a11;
    } else {
        d_Bext[m][n] = a00;       d_Bext[m][n + 1] = a01;
        d_Bext[m + 1][n] = a10;   d_Bext[m + 1][n + 1] = a11;
    }
}

// ---------------------------------------------------------------------------
// Gram: CTA = one 128x128 tile (3 unique symmetric tiles), split-K over KS=12
// (144 CTAs = one wave). Reads fp32 x, converts to bf16 hi/lo in-kernel,
// register double-buffered. Diagonal CTAs also accumulate row sums -> d_sp.
__global__ void __launch_bounds__(256) k_gram_mma(const float* __restrict__ x) {
    __shared__ __nv_bfloat16 sA[2][128][GR_PAD];
    __shared__ __nv_bfloat16 sB[2][128][GR_PAD];
    __shared__ float rs[128][2];
    const int tid = threadIdx.x, wid = tid >> 5, lane = tid & 31;
    const int t = blockIdx.x, ks = blockIdx.y, b = blockIdx.z;
    const int tr = (t == 2) ? 128 : 0, tc = (t == 0) ? 0 : 128;
    const bool diag = (t != 1);
    const int wm = (wid & 1) * 64, wn = (wid >> 1) * 32;
    float acc[4][4][4] = {};
    const int base = ks * 10 + (ks < 8 ? ks : 8);
    const int cnt  = (ks < 8) ? 11 : 10;

    const int r = tid >> 1, h = tid & 1;          // staging: row r, cols h*16..
    const float* xa = x + ((size_t)b * C + tr + r) * NSP;
    const float* xb = x + ((size_t)b * C + tc + r) * NSP;
    float ra[16], rb[16];
    float rsum = 0.f;

    // prologue load
#pragma unroll
    for (int j = 0; j < 4; j++)
        *(float4*)(ra + 4 * j) = *(const float4*)(xa + base * 32 + h * 16 + 4 * j);
    if (!diag)
#pragma unroll
        for (int j = 0; j < 4; j++)
            *(float4*)(rb + 4 * j) = *(const float4*)(xb + base * 32 + h * 16 + 4 * j);

    const uint32_t sAu = smem_u32(&sA[0][0][0]);
    const uint32_t sBu = diag ? sAu : smem_u32(&sB[0][0][0]);
    const uint32_t loP = 128 * GR_PAD * 2;        // hi->lo plane byte offset

    for (int c = 0; c < cnt; c++) {
        __syncthreads();                           // prior mma done with smem
        {   // convert + STS + rowsum
            __nv_bfloat16 hb[16], lb[16];
            split16(ra, hb, lb);
            *(uint4*)&sA[0][r][h * 16]     = *(uint4*)&hb[0];
            *(uint4*)&sA[0][r][h * 16 + 8] = *(uint4*)&hb[8];
            *(uint4*)&sA[1][r][h * 16]     = *(uint4*)&lb[0];
            *(uint4*)&sA[1][r][h * 16 + 8] = *(uint4*)&lb[8];
            if (diag) {
#pragma unroll
                for (int j = 0; j < 16; j++) rsum += ra[j];
            } else {
                split16(rb, hb, lb);
                *(uint4*)&sB[0][r][h * 16]     = *(uint4*)&hb[0];
                *(uint4*)&sB[0][r][h * 16 + 8] = *(uint4*)&hb[8];
                *(uint4*)&sB[1][r][h * 16]     = *(uint4*)&lb[0];
                *(uint4*)&sB[1][r][h * 16 + 8] = *(uint4*)&lb[8];
            }
        }
        __syncthreads();
        if (c + 1 < cnt) {                         // prefetch next chunk
            const int kb = (base + c + 1) * 32;
#pragma unroll
            for (int j = 0; j < 4; j++)
                *(float4*)(ra + 4 * j) = *(const float4*)(xa + kb + h * 16 + 4 * j);
            if (!diag)
#pragma unroll
                for (int j = 0; j < 4; j++)
                    *(float4*)(rb + 4 * j) = *(const float4*)(xb + kb + h * 16 + 4 * j);
        }
#pragma unroll
        for (int kk = 0; kk < 32; kk += 16) {
            uint32_t ah[4][4], al[4][4], bh[2][4], bl[2][4];
            const int arow = lane & 15, acol = kk + (lane >> 4) * 8;
#pragma unroll
            for (int i = 0; i < 4; i++) {
                uint32_t ad = sAu + (uint32_t)((wm + i * 16 + arow) * GR_PAD + acol) * 2;
                ldsm_x4(ah[i], ad);
                ldsm_x4(al[i], ad + loP);
            }
            const int bn = (lane & 7) + (lane >> 4) * 8;
            const int bcol = kk + ((lane >> 3) & 1) * 8;
#pragma unroll
            for (int j = 0; j < 2; j++) {
                uint32_t bd = sBu + (uint32_t)((wn + j * 16 + bn) * GR_PAD + bcol) * 2;
                ldsm_x4(bh[j], bd);
                ldsm_x4(bl[j], bd + loP);
            }
#pragma unroll
            for (int i = 0; i < 4; i++)
#pragma unroll
                for (int jj = 0; jj < 4; jj++) {
                    const uint32_t* ph = &bh[jj >> 1][(jj & 1) * 2];
                    const uint32_t* pl = &bl[jj >> 1][(jj & 1) * 2];
                    mma16816(acc[i][jj], ah[i], ph);
                    mma16816(acc[i][jj], ah[i], pl);
                    mma16816(acc[i][jj], al[i], ph);
                }
        }
    }
    // row-sum epilogue (diag CTAs cover all 256 rows exactly once)
    if (diag) {
        __syncthreads();
        rs[r][h] = rsum;
        __syncthreads();
        if (tid < 128) d_sp[ks][b][tr + tid] = rs[tid][0] + rs[tid][1];
    }
#pragma unroll
    for (int i = 0; i < 4; i++)
#pragma unroll
        for (int jj = 0; jj < 4; jj++) {
            int rl = wm + i * 16 + (lane >> 2);
            int cl = wn + jj * 8 + (lane & 3) * 2;
            *(float2*)&d_Gp[ks][b][t][rl][cl]     = make_float2(acc[i][jj][0], acc[i][jj][1]);
            *(float2*)&d_Gp[ks][b][t][rl + 8][cl] = make_float2(acc[i][jj][2], acc[i][jj][3]);
        }
}

// ---------------------------------------------------------------------------
// reduce split-K + rowsum partials -> S = G - s s^T/N (with mirror).
// grid (3, BATCH, 16): each CTA handles an 8-row slice of one 128x128 tile;
// one float4 per thread, 12-plane unrolled (MLP=12, full occupancy).
__global__ void __launch_bounds__(256) k_reduce_s() {
    const int t = blockIdx.x, b = blockIdx.y, z = blockIdx.z;
    const int tid = threadIdx.x;
    const int Rb = (t == 2) ? 128 : 0, Cb = (t == 0) ? 0 : 128;
    __shared__ float sR[8], sC[128];
    if (tid < 128) {
        float a = 0.f;
#pragma unroll
        for (int p = 0; p < KS; p++) a += d_sp[p][b][Cb + tid];
        sC[tid] = a;
    } else if (tid < 136) {
        float a = 0.f;
#pragma unroll
        for (int p = 0; p < KS; p++) a += d_sp[p][b][Rb + z * 8 + tid - 128];
        sR[tid - 128] = a;
    }
    __syncthreads();
    const int rl = tid >> 5;                       // 0..7 local row
    const int c4 = (tid & 31) * 4;
    const int row = z * 8 + rl;
    float4 a = make_float4(0.f, 0.f, 0.f, 0.f);
#pragma unroll
    for (int p = 0; p < KS; p++) {
        float4 v = *(const float4*)&d_Gp[p][b][t][row][c4];
        a.x += v.x; a.y += v.y; a.z += v.z; a.w += v.w;
    }
    const float sr = sR[rl] * INV_N;
    a.x -= sr * sC[c4];     a.y -= sr * sC[c4 + 1];
    a.z -= sr * sC[c4 + 2]; a.w -= sr * sC[c4 + 3];
    *(float4*)&d_S[b][Rb + row][Cb + c4] = a;
    if (t == 1) {
        d_S[b][Cb + c4][Rb + row]     = a.x;
        d_S[b][Cb + c4 + 1][Rb + row] = a.y;
        d_S[b][Cb + c4 + 2][Rb + row] = a.z;
        d_S[b][Cb + c4 + 3][Rb + row] = a.w;
    }
}

// ---------------------------------------------------------------------------
// T = S * Bext  (256 x 288, K=256) per batch
__global__ void __launch_bounds__(256) k_T() {
    const int b = blockIdx.z;
    const int m0 = blockIdx.y * 32, n0 = blockIdx.x * 32;
    __shared__ float As[32][33];
    __shared__ float Bs[32][33];
    const int tx = threadIdx.x & 15, ty = threadIdx.x >> 4;
    const int c0 = threadIdx.x & 31, r0 = threadIdx.x >> 5;
    float a00 = 0.f, a01 = 0.f, a10 = 0.f, a11 = 0.f;
    for (int k0 = 0; k0 < C; k0 += 32) {
#pragma unroll
        for (int p = 0; p < 4; p++) {
            int r = r0 + p * 8;
            As[c0][r] = d_S[b][m0 + r][k0 + c0];
            Bs[r][c0] = d_Bext[k0 + r][n0 + c0];
        }
        __syncthreads();
#pragma unroll
        for (int k = 0; k < 32; k++) {
            float a0 = As[k][ty * 2], a1 = As[k][ty * 2 + 1];
            float b0 = Bs[k][tx * 2], b1 = Bs[k][tx * 2 + 1];
            a00 += a0 * b0; a01 += a0 * b1; a10 += a1 * b0; a11 += a1 * b1;
        }
        __syncthreads();
    }
    const int m = m0 + ty * 2, n = n0 + tx * 2;
    d_T[b][m][n] = a00;     d_T[b][m][n + 1] = a01;
    d_T[b][m + 1][n] = a10; d_T[b][m + 1][n + 1] = a11;
}

// ---------------------------------------------------------------------------
// W = A * T (store hi/lo), col 256 -> beff = A S v + out_b
__global__ void __launch_bounds__(256) k_W(const float* __restrict__ out_b) {
    const int b = blockIdx.z;
    const int m0 = blockIdx.y * 32, n0 = blockIdx.x * 32;
    __shared__ float As[32][33];
    __shared__ float Bs[32][33];
    const int tx = threadIdx.x & 15, ty = threadIdx.x >> 4;
    const int c0 = threadIdx.x & 31, r0 = threadIdx.x >> 5;
    float a00 = 0.f, a01 = 0.f, a10 = 0.f, a11 = 0.f;
    for (int k0 = 0; k0 < C; k0 += 32) {
#pragma unroll
        for (int p = 0; p < 4; p++) {
            int r = r0 + p * 8;
            As[c0][r] = d_A[(m0 + r) * C + k0 + c0];
            Bs[r][c0] = d_T[b][k0 + r][n0 + c0];
        }
        __syncthreads();
#pragma unroll
        for (int k = 0; k < 32; k++) {
            float a0 = As[k][ty * 2], a1 = As[k][ty * 2 + 1];
            float b0 = Bs[k][tx * 2], b1 = Bs[k][tx * 2 + 1];
            a00 += a0 * b0; a01 += a0 * b1; a10 += a1 * b0; a11 += a1 * b1;
        }
        __syncthreads();
    }
    const int m = m0 + ty * 2, n = n0 + tx * 2;
    float vals[2][2] = {{a00, a01}, {a10, a11}};
#pragma unroll
    for (int i = 0; i < 2; i++)
#pragma unroll
        for (int j = 0; j < 2; j++) {
            int mm = m + i, nn = n + j;
            float v = vals[i][j];
            if (nn < C) {
                __nv_bfloat16 hh = __float2bfloat16(v);
                d_Whi[b][mm][nn] = hh;
                d_Wlo[b][mm][nn] = __float2bfloat16(v - __bfloat162float(hh));
            } else if (nn == C) {
                d_beff[b][mm] = v + out_b[mm];
            }
        }
}

// ---------------------------------------------------------------------------
// apply: out = x + W x + beff. CTA 128(ch) x 128(sp), K=256.
// W tiles from d_Whi/d_Wlo; x tiles fp32->bf16 converted in-kernel.
__global__ void __launch_bounds__(256) k_apply_mma(const float* __restrict__ x,
                                                   float* __restrict__ outp) {
    __shared__ __nv_bfloat16 sW[2][128][GR_PAD];
    __shared__ __nv_bfloat16 sX[2][32][AP_BPAD];
    const int tid = threadIdx.x, wid = tid >> 5, lane = tid & 31;
    const int m0 = blockIdx.y * 128, n0 = blockIdx.x * 128, b = blockIdx.z;
    const int wm = (wid & 1) * 64, wn = (wid >> 1) * 32;
    float acc[4][4][4] = {};

    const int rw = tid >> 1, hw = tid & 1;         // W staging
    const int xr = tid >> 3, xh = tid & 7;         // x staging
    uint4 wh[2], wl[2];
    float xf[16];

    // prologue load (chunk 0)
    wh[0] = *(const uint4*)&d_Whi[b][m0 + rw][hw * 16];
    wh[1] = *(const uint4*)&d_Whi[b][m0 + rw][hw * 16 + 8];
    wl[0] = *(const uint4*)&d_Wlo[b][m0 + rw][hw * 16];
    wl[1] = *(const uint4*)&d_Wlo[b][m0 + rw][hw * 16 + 8];
#pragma unroll
    for (int j = 0; j < 4; j++)
        *(float4*)(xf + 4 * j) =
            *(const float4*)(x + ((size_t)b * C + xr) * NSP + n0 + xh * 16 + 4 * j);

    const uint32_t sWu = smem_u32(&sW[0][0][0]);
    const uint32_t sXu = smem_u32(&sX[0][0][0]);
    const uint32_t loW = 128 * GR_PAD * 2;
    const uint32_t loX = 32 * AP_BPAD * 2;

    for (int kc = 0; kc < 8; kc++) {
        __syncthreads();
        {   // stage W + convert x
            *(uint4*)&sW[0][rw][hw * 16]     = wh[0];
            *(uint4*)&sW[0][rw][hw * 16 + 8] = wh[1];
            *(uint4*)&sW[1][rw][hw * 16]     = wl[0];
            *(uint4*)&sW[1][rw][hw * 16 + 8] = wl[1];
            __nv_bfloat16 hb[16], lb[16];
            split16(xf, hb, lb);
            *(uint4*)&sX[0][xr][xh * 16]     = *(uint4*)&hb[0];
            *(uint4*)&sX[0][xr][xh * 16 + 8] = *(uint4*)&hb[8];
            *(uint4*)&sX[1][xr][xh * 16]     = *(uint4*)&lb[0];
            *(uint4*)&sX[1][xr][xh * 16 + 8] = *(uint4*)&lb[8];
        }
        __syncthreads();
        if (kc + 1 < 8) {                          // prefetch next chunk
            const int kb = (kc + 1) * 32;
            wh[0] = *(const uint4*)&d_Whi[b][m0 + rw][kb + hw * 16];
            wh[1] = *(const uint4*)&d_Whi[b][m0 + rw][kb + hw * 16 + 8];
            wl[0] = *(const uint4*)&d_Wlo[b][m0 + rw][kb + hw * 16];
            wl[1] = *(const uint4*)&d_Wlo[b][m0 + rw][kb + hw * 16 + 8];
#pragma unroll
            for (int j = 0; j < 4; j++)
                *(float4*)(xf + 4 * j) =
                    *(const float4*)(x + ((size_t)b * C + kb + xr) * NSP + n0 + xh * 16 + 4 * j);
        }
#pragma unroll
        for (int kk = 0; kk < 32; kk += 16) {
            uint32_t ah[4][4], al[4][4], bh[2][4], bl[2][4];
            const int arow = lane & 15, acol = kk + (lane >> 4) * 8;
#pragma unroll
            for (int i = 0; i < 4; i++) {
                uint32_t ad = sWu + (uint32_t)((wm + i * 16 + arow) * GR_PAD + acol) * 2;
                ldsm_x4(ah[i], ad);
                ldsm_x4(al[i], ad + loW);
            }
            const int krow = kk + (lane & 7) + ((lane >> 3) & 1) * 8;
            const int ncol = ((lane >> 4) & 1) * 8;
#pragma unroll
            for (int j = 0; j < 2; j++) {
                uint32_t bd = sXu + (uint32_t)(krow * AP_BPAD + wn + j * 16 + ncol) * 2;
                ldsm_x4_t(bh[j], bd);
                ldsm_x4_t(bl[j], bd + loX);
            }
#pragma unroll
            for (int i = 0; i < 4; i++)
#pragma unroll
                for (int jj = 0; jj < 4; jj++) {
                    const uint32_t* ph = &bh[jj >> 1][(jj & 1) * 2];
                    const uint32_t* pl = &bl[jj >> 1][(jj & 1) * 2];
                    mma16816(acc[i][jj], ah[i], ph);
                    mma16816(acc[i][jj], ah[i], pl);
                    mma16816(acc[i][jj], al[i], ph);
                }
        }
    }
    // epilogue: + x + beff
#pragma unroll
    for (int i = 0; i < 4; i++) {
        int r0g = m0 + wm + i * 16 + (lane >> 2);
        float be0 = d_beff[b][r0g], be1 = d_beff[b][r0g + 8];
        const float* x0 = x + ((size_t)b * C + r0g) * NSP + n0;
        float* o0 = outp + ((size_t)b * C + r0g) * NSP + n0;
#pragma unroll
        for (int jj = 0; jj < 4; jj++) {
            int cl = wn + jj * 8 + (lane & 3) * 2;
            float2 xa = *(const float2*)(x0 + cl);
            float2 xb = *(const float2*)(x0 + 8 * NSP + cl);
            float2 oa = make_float2(acc[i][jj][0] + xa.x + be0, acc[i][jj][1] + xa.y + be0);
            float2 ob = make_float2(acc[i][jj][2] + xb.x + be1, acc[i][jj][3] + xb.y + be1);
            *(float2*)(o0 + cl) = oa;
            *(float2*)(o0 + 8 * NSP + cl) = ob;
        }
    }
}

// ---------------------------------------------------------------------------
extern "C" void kernel_launch(void* const* d_in, const int* in_sizes, int n_in,
                              void* d_out, int out_size) {
    const float* x       = (const float*)d_in[0];
    const float* g_w     = (const float*)d_in[1];
    const float* theta_w = (const float*)d_in[3];
    const float* theta_b = (const float*)d_in[4];
    const float* phi_w   = (const float*)d_in[5];
    const float* out_w   = (const float*)d_in[7];
    const float* out_b   = (const float*)d_in[8];
    float* out = (float*)d_out;

    k_theta_prep<<<C, 128>>>(theta_w, theta_b);
    k_ab<<<dim3(NB / 32, C / 32, 2), 256>>>(out_w, g_w, phi_w);
    k_gram_mma<<<dim3(3, KS, BATCH), 256>>>(x);
    k_reduce_s<<<dim3(3, BATCH, 16), 256>>>();
    k_T<<<dim3(NB / 32, C / 32, BATCH), 256>>>();
    k_W<<<dim3(NB / 32, C / 32, BATCH), 256>>>(out_b);
    k_apply_mma<<<dim3(NSP / 128, C / 128, BATCH), 256>>>(x, out);
}

// round 14
// speedup vs baseline: 1.3690x; 1.1460x over previous
#include <cuda_runtime.h>
#include <cuda_fp16.h>
#include <cstdint>

// ---------------------------------------------------------------------------
// NonLocal2D collapsed to per-batch affine map:
//   S = x x^T - s s^T/N,  W = A S B,  beff = A S v + out_b,
//   A = out_w g_w,  B = phi^T theta',  v = phi^T theta'_b   (batch-independent)
//   out = x + W x + beff.
// R12/R13: fp16 hi/lo split (10-bit mantissa -> residual 2^-12), 2-pass MMA
//   (hi*hi + hi*lo; dropped lo*hi term ~2.4e-4 rel, under 1e-3 budget).
//   W stored fp16-hi only. 33% fewer MMAs + fewer ldsm vs R11's bf16 3-pass.
// ---------------------------------------------------------------------------

#define BATCH 4
#define C     256
#define CI    128
#define NSP   4096
#define KS    12
#define INV_N (1.0f / 4096.0f)
#define GR_PAD 40              // fp16 row stride 80B: ldmatrix conflict-free
#define AP_BPAD 136            // fp16 row stride 272B: trans-ldmatrix conflict-free
#define NB    288              // padded N for Bext/T (256 W cols + beff col + pad)

// ------------------------- device scratch ----------------------------------
__device__ float d_Gp[KS][BATCH][3][128][128];
__device__ float d_sp[KS][BATCH][C];
__device__ float d_S [BATCH][C][C];
__device__ float d_thpw[CI * C];
__device__ float d_thpb[CI];
__device__ float d_A   [C * C];
__device__ float d_Bext[C][NB];
__device__ float d_T [BATCH][C][NB];
__device__ __half d_Whi[BATCH][C][C];
__device__ float d_beff[BATCH][C];

// ------------------------- helpers -----------------------------------------
__device__ __forceinline__ uint32_t smem_u32(const void* p) {
    uint32_t a;
    asm("{ .reg .u64 t; cvta.to.shared.u64 t, %1; cvt.u32.u64 %0, t; }"
        : "=r"(a) : "l"(p));
    return a;
}
__device__ __forceinline__ void ldsm_x4(uint32_t* r, uint32_t addr) {
    asm volatile("ldmatrix.sync.aligned.m8n8.x4.shared.b16 {%0,%1,%2,%3}, [%4];"
                 : "=r"(r[0]), "=r"(r[1]), "=r"(r[2]), "=r"(r[3]) : "r"(addr));
}
__device__ __forceinline__ void ldsm_x4_t(uint32_t* r, uint32_t addr) {
    asm volatile("ldmatrix.sync.aligned.m8n8.x4.trans.shared.b16 {%0,%1,%2,%3}, [%4];"
                 : "=r"(r[0]), "=r"(r[1]), "=r"(r[2]), "=r"(r[3]) : "r"(addr));
}
__device__ __forceinline__ void mma16816(float* d, const uint32_t* a, const uint32_t* b) {
    asm volatile(
        "mma.sync.aligned.m16n8k16.row.col.f32.f16.f16.f32 "
        "{%0,%1,%2,%3}, {%4,%5,%6,%7}, {%8,%9}, {%0,%1,%2,%3};"
        : "+f"(d[0]), "+f"(d[1]), "+f"(d[2]), "+f"(d[3])
        : "r"(a[0]), "r"(a[1]), "r"(a[2]), "r"(a[3]), "r"(b[0]), "r"(b[1]));
}
__device__ __forceinline__ void split16(const float* f, __half* h, __half* l) {
#pragma unroll
    for (int j = 0; j < 16; j++) {
        h[j] = __float2half(f[j]);
        l[j] = __float2half(f[j] - __half2float(h[j]));
    }
}

// ---------------------------------------------------------------------------
// theta' prep
__global__ void k_theta_prep(const float* __restrict__ tw, const float* __restrict__ tb) {
    const int c = blockIdx.x, o = threadIdx.x;     // 256 blocks x 128 threads
    __shared__ float sm[128];
    float v = tw[o * C + c];
    sm[o] = v; __syncthreads();
    for (int s = 64; s > 0; s >>= 1) { if (o < s) sm[o] += sm[o + s]; __syncthreads(); }
    d_thpw[o * C + c] = v - sm[0] * (1.0f / CI);
    if (c == 0) {
        float vb = tb[o];
        __syncthreads();
        sm[o] = vb; __syncthreads();
        for (int s = 64; s > 0; s >>= 1) { if (o < s) sm[o] += sm[o + s]; __syncthreads(); }
        d_thpb[o] = vb - sm[0] * (1.0f / CI);
    }
}

// ---------------------------------------------------------------------------
// A = out_w g_w (z=0), Bext = [phi^T theta' | phi^T theta'_b | 0] (z=1). K=128.
__global__ void __launch_bounds__(256) k_ab(const float* __restrict__ out_w,
                                            const float* __restrict__ g_w,
                                            const float* __restrict__ phi_w) {
    const int z = blockIdx.z;
    const int m0 = blockIdx.y * 32, n0 = blockIdx.x * 32;
    if (z == 0 && n0 >= C) return;
    __shared__ float As[32][33];
    __shared__ float Bs[32][33];
    const int tx = threadIdx.x & 15, ty = threadIdx.x >> 4;
    const int c0 = threadIdx.x & 31, r0 = threadIdx.x >> 5;
    float a00 = 0.f, a01 = 0.f, a10 = 0.f, a11 = 0.f;
    for (int k0 = 0; k0 < CI; k0 += 32) {
#pragma unroll
        for (int p = 0; p < 4; p++) {
            int r = r0 + p * 8;
            As[c0][r] = z == 0 ? out_w[(m0 + r) * CI + k0 + c0]
                               : phi_w[(k0 + c0) * C + m0 + r];
            int n = n0 + c0;
            float bv;
            if (z == 0)          bv = g_w[(k0 + r) * C + n];
            else if (n < C)      bv = d_thpw[(k0 + r) * C + n];
            else if (n == C)     bv = d_thpb[k0 + r];
            else                 bv = 0.f;
            Bs[r][c0] = bv;
        }
        __syncthreads();
#pragma unroll
        for (int k = 0; k < 32; k++) {
            float a0 = As[k][ty * 2], a1 = As[k][ty * 2 + 1];
            float b0 = Bs[k][tx * 2], b1 = Bs[k][tx * 2 + 1];
            a00 += a0 * b0; a01 += a0 * b1; a10 += a1 * b0; a11 += a1 * b1;
        }
        __syncthreads();
    }
    const int m = m0 + ty * 2, n = n0 + tx * 2;
    if (z == 0) {
        d_A[m * C + n] = a00;       d_A[m * C + n + 1] = a01;
        d_A[(m + 1) * C + n] = a10; d_A[(m + 1) * C + n + 1] = a11;
    } else {
        d_Bext[m][n] = a00;       d_Bext[m][n + 1] = a01;
        d_Bext[m + 1][n] = a10;   d_Bext[m + 1][n + 1] = a11;
    }
}

// ---------------------------------------------------------------------------
// Gram: CTA = one 128x128 tile (3 unique symmetric tiles), split-K over KS=12
// (144 CTAs = one wave). fp16 2-pass: G ~= hiA*(hiB + loB); A-side lo never
// staged/loaded. Diagonal CTAs also accumulate row sums -> d_sp.
__global__ void __launch_bounds__(256) k_gram_mma(const float* __restrict__ x) {
    __shared__ __half sA[2][128][GR_PAD];
    __shared__ __half sB[2][128][GR_PAD];
    __shared__ float rs[128][2];
    const int tid = threadIdx.x, wid = tid >> 5, lane = tid & 31;
    const int t = blockIdx.x, ks = blockIdx.y, b = blockIdx.z;
    const int tr = (t == 2) ? 128 : 0, tc = (t == 0) ? 0 : 128;
    const bool diag = (t != 1);
    const int wm = (wid & 1) * 64, wn = (wid >> 1) * 32;
    float acc[4][4][4] = {};
    const int base = ks * 10 + (ks < 8 ? ks : 8);
    const int cnt  = (ks < 8) ? 11 : 10;

    const int r = tid >> 1, h = tid & 1;          // staging: row r, cols h*16..
    const float* xa = x + ((size_t)b * C + tr + r) * NSP;
    const float* xb = x + ((size_t)b * C + tc + r) * NSP;
    float ra[16], rb[16];
    float rsum = 0.f;

    // prologue load
#pragma unroll
    for (int j = 0; j < 4; j++)
        *(float4*)(ra + 4 * j) = *(const float4*)(xa + base * 32 + h * 16 + 4 * j);
    if (!diag)
#pragma unroll
        for (int j = 0; j < 4; j++)
            *(float4*)(rb + 4 * j) = *(const float4*)(xb + base * 32 + h * 16 + 4 * j);

    const uint32_t sAu = smem_u32(&sA[0][0][0]);
    const uint32_t sBu = diag ? sAu : smem_u32(&sB[0][0][0]);
    const uint32_t loP = 128 * GR_PAD * 2;        // hi->lo plane byte offset

    for (int c = 0; c < cnt; c++) {
        __syncthreads();                           // prior mma done with smem
        {   // convert + STS + rowsum
            __half hb[16], lb[16];
            split16(ra, hb, lb);
            *(uint4*)&sA[0][r][h * 16]     = *(uint4*)&hb[0];
            *(uint4*)&sA[0][r][h * 16 + 8] = *(uint4*)&hb[8];
            if (diag) {
                // A doubles as B: lo plane needed for the hi*lo pass
                *(uint4*)&sA[1][r][h * 16]     = *(uint4*)&lb[0];
                *(uint4*)&sA[1][r][h * 16 + 8] = *(uint4*)&lb[8];
#pragma unroll
                for (int j = 0; j < 16; j++) rsum += ra[j];
            } else {
                split16(rb, hb, lb);
                *(uint4*)&sB[0][r][h * 16]     = *(uint4*)&hb[0];
                *(uint4*)&sB[0][r][h * 16 + 8] = *(uint4*)&hb[8];
                *(uint4*)&sB[1][r][h * 16]     = *(uint4*)&lb[0];
                *(uint4*)&sB[1][r][h * 16 + 8] = *(uint4*)&lb[8];
            }
        }
        __syncthreads();
        if (c + 1 < cnt) {                         // prefetch next chunk
            const int kb = (base + c + 1) * 32;
#pragma unroll
            for (int j = 0; j < 4; j++)
                *(float4*)(ra + 4 * j) = *(const float4*)(xa + kb + h * 16 + 4 * j);
            if (!diag)
#pragma unroll
                for (int j = 0; j < 4; j++)
                    *(float4*)(rb + 4 * j) = *(const float4*)(xb + kb + h * 16 + 4 * j);
        }
#pragma unroll
        for (int kk = 0; kk < 32; kk += 16) {
            uint32_t ah[4][4], bh[2][4], bl[2][4];
            const int arow = lane & 15, acol = kk + (lane >> 4) * 8;
#pragma unroll
            for (int i = 0; i < 4; i++) {
                uint32_t ad = sAu + (uint32_t)((wm + i * 16 + arow) * GR_PAD + acol) * 2;
                ldsm_x4(ah[i], ad);
            }
            const int bn = (lane & 7) + (lane >> 4) * 8;
            const int bcol = kk + ((lane >> 3) & 1) * 8;
#pragma unroll
            for (int j = 0; j < 2; j++) {
                uint32_t bd = sBu + (uint32_t)((wn + j * 16 + bn) * GR_PAD + bcol) * 2;
                ldsm_x4(bh[j], bd);
                ldsm_x4(bl[j], bd + loP);
            }
#pragma unroll
            for (int i = 0; i < 4; i++)
#pragma unroll
                for (int jj = 0; jj < 4; jj++) {
                    const uint32_t* ph = &bh[jj >> 1][(jj & 1) * 2];
                    const uint32_t* pl = &bl[jj >> 1][(jj & 1) * 2];
                    mma16816(acc[i][jj], ah[i], ph);
                    mma16816(acc[i][jj], ah[i], pl);
                }
        }
    }
    // row-sum epilogue (diag CTAs cover all 256 rows exactly once)
    if (diag) {
        __syncthreads();
        rs[r][h] = rsum;
        __syncthreads();
        if (tid < 128) d_sp[ks][b][tr + tid] = rs[tid][0] + rs[tid][1];
    }
#pragma unroll
    for (int i = 0; i < 4; i++)
#pragma unroll
        for (int jj = 0; jj < 4; jj++) {
            int rl = wm + i * 16 + (lane >> 2);
            int cl = wn + jj * 8 + (lane & 3) * 2;
            *(float2*)&d_Gp[ks][b][t][rl][cl]     = make_float2(acc[i][jj][0], acc[i][jj][1]);
            *(float2*)&d_Gp[ks][b][t][rl + 8][cl] = make_float2(acc[i][jj][2], acc[i][jj][3]);
        }
}

// ---------------------------------------------------------------------------
// reduce split-K + rowsum partials -> S = G - s s^T/N (with mirror).
// grid (3, BATCH, 16): 8-row slice per CTA, 1 float4/thread, 12-plane unroll.
__global__ void __launch_bounds__(256) k_reduce_s() {
    const int t = blockIdx.x, b = blockIdx.y, z = blockIdx.z;
    const int tid = threadIdx.x;
    const int Rb = (t == 2) ? 128 : 0, Cb = (t == 0) ? 0 : 128;
    __shared__ float sR[8], sC[128];
    if (tid < 128) {
        float a = 0.f;
#pragma unroll
        for (int p = 0; p < KS; p++) a += d_sp[p][b][Cb + tid];
        sC[tid] = a;
    } else if (tid < 136) {
        float a = 0.f;
#pragma unroll
        for (int p = 0; p < KS; p++) a += d_sp[p][b][Rb + z * 8 + tid - 128];
        sR[tid - 128] = a;
    }
    __syncthreads();
    const int rl = tid >> 5;                       // 0..7 local row
    const int c4 = (tid & 31) * 4;
    const int row = z * 8 + rl;
    float4 a = make_float4(0.f, 0.f, 0.f, 0.f);
#pragma unroll
    for (int p = 0; p < KS; p++) {
        float4 v = *(const float4*)&d_Gp[p][b][t][row][c4];
        a.x += v.x; a.y += v.y; a.z += v.z; a.w += v.w;
    }
    const float sr = sR[rl] * INV_N;
    a.x -= sr * sC[c4];     a.y -= sr * sC[c4 + 1];
    a.z -= sr * sC[c4 + 2]; a.w -= sr * sC[c4 + 3];
    *(float4*)&d_S[b][Rb + row][Cb + c4] = a;
    if (t == 1) {
        d_S[b][Cb + c4][Rb + row]     = a.x;
        d_S[b][Cb + c4 + 1][Rb + row] = a.y;
        d_S[b][Cb + c4 + 2][Rb + row] = a.z;
        d_S[b][Cb + c4 + 3][Rb + row] = a.w;
    }
}

// ---------------------------------------------------------------------------
// T = S * Bext  (256 x 288, K=256) per batch
__global__ void __launch_bounds__(256) k_T() {
    const int b = blockIdx.z;
    const int m0 = blockIdx.y * 32, n0 = blockIdx.x * 32;
    __shared__ float As[32][33];
    __shared__ float Bs[32][33];
    const int tx = threadIdx.x & 15, ty = threadIdx.x >> 4;
    const int c0 = threadIdx.x & 31, r0 = threadIdx.x >> 5;
    float a00 = 0.f, a01 = 0.f, a10 = 0.f, a11 = 0.f;
    for (int k0 = 0; k0 < C; k0 += 32) {
#pragma unroll
        for (int p = 0; p < 4; p++) {
            int r = r0 + p * 8;
            As[c0][r] = d_S[b][m0 + r][k0 + c0];
            Bs[r][c0] = d_Bext[k0 + r][n0 + c0];
        }
        __syncthreads();
#pragma unroll
        for (int k = 0; k < 32; k++) {
            float a0 = As[k][ty * 2], a1 = As[k][ty * 2 + 1];
            float b0 = Bs[k][tx * 2], b1 = Bs[k][tx * 2 + 1];
            a00 += a0 * b0; a01 += a0 * b1; a10 += a1 * b0; a11 += a1 * b1;
        }
        __syncthreads();
    }
    const int m = m0 + ty * 2, n = n0 + tx * 2;
    d_T[b][m][n] = a00;     d_T[b][m][n + 1] = a01;
    d_T[b][m + 1][n] = a10; d_T[b][m + 1][n + 1] = a11;
}

// ---------------------------------------------------------------------------
// W = A * T (store fp16 hi), col 256 -> beff = A S v + out_b
__global__ void __launch_bounds__(256) k_W(const float* __restrict__ out_b) {
    const int b = blockIdx.z;
    const int m0 = blockIdx.y * 32, n0 = blockIdx.x * 32;
    __shared__ float As[32][33];
    __shared__ float Bs[32][33];
    const int tx = threadIdx.x & 15, ty = threadIdx.x >> 4;
    const int c0 = threadIdx.x & 31, r0 = threadIdx.x >> 5;
    float a00 = 0.f, a01 = 0.f, a10 = 0.f, a11 = 0.f;
    for (int k0 = 0; k0 < C; k0 += 32) {
#pragma unroll
        for (int p = 0; p < 4; p++) {
            int r = r0 + p * 8;
            As[c0][r] = d_A[(m0 + r) * C + k0 + c0];
            Bs[r][c0] = d_T[b][k0 + r][n0 + c0];
        }
        __syncthreads();
#pragma unroll
        for (int k = 0; k < 32; k++) {
            float a0 = As[k][ty * 2], a1 = As[k][ty * 2 + 1];
            float b0 = Bs[k][tx * 2], b1 = Bs[k][tx * 2 + 1];
            a00 += a0 * b0; a01 += a0 * b1; a10 += a1 * b0; a11 += a1 * b1;
        }
        __syncthreads();
    }
    const int m = m0 + ty * 2, n = n0 + tx * 2;
    float vals[2][2] = {{a00, a01}, {a10, a11}};
#pragma unroll
    for (int i = 0; i < 2; i++)
#pragma unroll
        for (int j = 0; j < 2; j++) {
            int mm = m + i, nn = n + j;
            float v = vals[i][j];
            if (nn < C)       d_Whi[b][mm][nn] = __float2half(v);
            else if (nn == C) d_beff[b][mm] = v + out_b[mm];
        }
}

// ---------------------------------------------------------------------------
// apply: out = x + W x + beff. CTA 128(ch) x 128(sp), K=256, fp16 2-pass:
// W*x ~= Whi*(xhi + xlo). W staged hi-only; x fp32->fp16 split in-kernel.
__global__ void __launch_bounds__(256) k_apply_mma(const float* __restrict__ x,
                                                   float* __restrict__ outp) {
    __shared__ __half sW[128][GR_PAD];
    __shared__ __half sX[2][32][AP_BPAD];
    const int tid = threadIdx.x, wid = tid >> 5, lane = tid & 31;
    const int m0 = blockIdx.y * 128, n0 = blockIdx.x * 128, b = blockIdx.z;
    const int wm = (wid & 1) * 64, wn = (wid >> 1) * 32;
    float acc[4][4][4] = {};

    const int rw = tid >> 1, hw = tid & 1;         // W staging
    const int xr = tid >> 3, xh = tid & 7;         // x staging
    uint4 wh[2];
    float xf[16];

    // prologue load (chunk 0)
    wh[0] = *(const uint4*)&d_Whi[b][m0 + rw][hw * 16];
    wh[1] = *(const uint4*)&d_Whi[b][m0 + rw][hw * 16 + 8];
#pragma unroll
    for (int j = 0; j < 4; j++)
        *(float4*)(xf + 4 * j) =
            *(const float4*)(x + ((size_t)b * C + xr) * NSP + n0 + xh * 16 + 4 * j);

    const uint32_t sWu = smem_u32(&sW[0][0]);
    const uint32_t sXu = smem_u32(&sX[0][0][0]);
    const uint32_t loX = 32 * AP_BPAD * 2;

    for (int kc = 0; kc < 8; kc++) {
        __syncthreads();
        {   // stage W + convert x
            *(uint4*)&sW[rw][hw * 16]     = wh[0];
            *(uint4*)&sW[rw][hw * 16 + 8] = wh[1];
            __half hb[16], lb[16];
            split16(xf, hb, lb);
            *(uint4*)&sX[0][xr][xh * 16]     = *(uint4*)&hb[0];
            *(uint4*)&sX[0][xr][xh * 16 + 8] = *(uint4*)&hb[8];
            *(uint4*)&sX[1][xr][xh * 16]     = *(uint4*)&lb[0];
            *(uint4*)&sX[1][xr][xh * 16 + 8] = *(uint4*)&lb[8];
        }
        __syncthreads();
        if (kc + 1 < 8) {                          // prefetch next chunk
            const int kb = (kc + 1) * 32;
            wh[0] = *(const uint4*)&d_Whi[b][m0 + rw][kb + hw * 16];
            wh[1] = *(const uint4*)&d_Whi[b][m0 + rw][kb + hw * 16 + 8];
#pragma unroll
            for (int j = 0; j < 4; j++)
                *(float4*)(xf + 4 * j) =
                    *(const float4*)(x + ((size_t)b * C + kb + xr) * NSP + n0 + xh * 16 + 4 * j);
        }
#pragma unroll
        for (int kk = 0; kk < 32; kk += 16) {
            uint32_t ah[4][4], bh[2][4], bl[2][4];
            const int arow = lane & 15, acol = kk + (lane >> 4) * 8;
#pragma unroll
            for (int i = 0; i < 4; i++) {
                uint32_t ad = sWu + (uint32_t)((wm + i * 16 + arow) * GR_PAD + acol) * 2;
                ldsm_x4(ah[i], ad);
            }
            const int krow = kk + (lane & 7) + ((lane >> 3) & 1) * 8;
            const int ncol = ((lane >> 4) & 1) * 8;
#pragma unroll
            for (int j = 0; j < 2; j++) {
                uint32_t bd = sXu + (uint32_t)(krow * AP_BPAD + wn + j * 16 + ncol) * 2;
                ldsm_x4_t(bh[j], bd);
                ldsm_x4_t(bl[j], bd + loX);
            }
#pragma unroll
            for (int i = 0; i < 4; i++)
#pragma unroll
                for (int jj = 0; jj < 4; jj++) {
                    const uint32_t* ph = &bh[jj >> 1][(jj & 1) * 2];
                    const uint32_t* pl = &bl[jj >> 1][(jj & 1) * 2];
                    mma16816(acc[i][jj], ah[i], ph);
                    mma16816(acc[i][jj], ah[i], pl);
                }
        }
    }
    // epilogue: + x + beff
#pragma unroll
    for (int i = 0; i < 4; i++) {
        int r0g = m0 + wm + i * 16 + (lane >> 2);
        float be0 = d_beff[b][r0g], be1 = d_beff[b][r0g + 8];
        const float* x0 = x + ((size_t)b * C + r0g) * NSP + n0;
        float* o0 = outp + ((size_t)b * C + r0g) * NSP + n0;
#pragma unroll
        for (int jj = 0; jj < 4; jj++) {
            int cl = wn + jj * 8 + (lane & 3) * 2;
            float2 xa = *(const float2*)(x0 + cl);
            float2 xb = *(const float2*)(x0 + 8 * NSP + cl);
            float2 oa = make_float2(acc[i][jj][0] + xa.x + be0, acc[i][jj][1] + xa.y + be0);
            float2 ob = make_float2(acc[i][jj][2] + xb.x + be1, acc[i][jj][3] + xb.y + be1);
            *(float2*)(o0 + cl) = oa;
            *(float2*)(o0 + 8 * NSP + cl) = ob;
        }
    }
}

// ---------------------------------------------------------------------------
extern "C" void kernel_launch(void* const* d_in, const int* in_sizes, int n_in,
                              void* d_out, int out_size) {
    const float* x       = (const float*)d_in[0];
    const float* g_w     = (const float*)d_in[1];
    const float* theta_w = (const float*)d_in[3];
    const float* theta_b = (const float*)d_in[4];
    const float* phi_w   = (const float*)d_in[5];
    const float* out_w   = (const float*)d_in[7];
    const float* out_b   = (const float*)d_in[8];
    float* out = (float*)d_out;

    k_theta_prep<<<C, 128>>>(theta_w, theta_b);
    k_ab<<<dim3(NB / 32, C / 32, 2), 256>>>(out_w, g_w, phi_w);
    k_gram_mma<<<dim3(3, KS, BATCH), 256>>>(x);
    k_reduce_s<<<dim3(3, BATCH, 16), 256>>>();
    k_T<<<dim3(NB / 32, C / 32, BATCH), 256>>>();
    k_W<<<dim3(NB / 32, C / 32, BATCH), 256>>>(out_b);
    k_apply_mma<<<dim3(NSP / 128, C / 128, BATCH), 256>>>(x, out);
}